// round 14
// baseline (speedup 1.0000x reference)
#include <cuda_runtime.h>
#include <cuda_bf16.h>

#define N_NEURON 128
#define N_RULES  512
#define BATCH    4096

// Probe: 3 neuron rows (12 x LDG.128) front-batched per iteration, with
// __launch_bounds__(128, 6) granting an ~85-reg budget so ptxas keeps the
// batch live (R10 showed that without an explicit budget it de-batches).
// 6 CTAs/SM x 4 warps = 24 warps/SM, 12 x 512B = 147 KB/SM in flight.
// N_NEURON = 128 is not divisible by 3: loop does 42 iters of 3 + tail of 2.
__global__ void __launch_bounds__(128, 6) lei_fused_kernel(
    const float* __restrict__ x,
    const float* __restrict__ head_w,
    const float* __restrict__ head_b,
    const float* __restrict__ foot_w,
    const float* __restrict__ foot_b,
    float* __restrict__ out)
{
    const int warp = threadIdx.x >> 5;
    const int lane = threadIdx.x & 31;
    const int b = blockIdx.x * 4 + warp;   // 1024 blocks * 4 warps = 4096

    const float* __restrict__ fw0 = foot_w;            // [128]
    const float* __restrict__ fw1 = foot_w + N_NEURON; // [128]

    float acc0 = 0.0f, acc1 = 0.0f;

    // Fold the head bias contribution: sum_n head_b[n]*fw_j[n], split across lanes.
#pragma unroll
    for (int k = 0; k < 4; k++) {
        int n = 32 * k + lane;
        float hb = head_b[n];
        acc0 = fmaf(hb, fw0[n], acc0);
        acc1 = fmaf(hb, fw1[n], acc1);
    }

    const float4* __restrict__ xb =
        reinterpret_cast<const float4*>(x) + (size_t)b * (N_RULES / 4);
    const size_t nstride = (size_t)BATCH * (N_RULES / 4);  // float4 stride between neurons
    const float4* __restrict__ wq = reinterpret_cast<const float4*>(head_w);

    // Main loop: 42 iterations x 3 neurons = 126.
    for (int n = 0; n < 126; n += 3) {
        float4 xv[12];
#pragma unroll
        for (int r = 0; r < 3; r++) {
            const float4* p = xb + (size_t)(n + r) * nstride;
#pragma unroll
            for (int k = 0; k < 4; k++)
                xv[4 * r + k] = p[lane + 32 * k];
        }

#pragma unroll
        for (int r = 0; r < 3; r++) {
            float pa = 0.0f;
            const float4* w = wq + (size_t)(n + r) * (N_RULES / 4);
#pragma unroll
            for (int k = 0; k < 4; k++) {
                float4 wv = w[lane + 32 * k];
                pa = fmaf(xv[4 * r + k].x, wv.x, pa);
                pa = fmaf(xv[4 * r + k].y, wv.y, pa);
                pa = fmaf(xv[4 * r + k].z, wv.z, pa);
                pa = fmaf(xv[4 * r + k].w, wv.w, pa);
            }
            acc0 = fmaf(pa, fw0[n + r], acc0);
            acc1 = fmaf(pa, fw1[n + r], acc1);
        }
    }

    // Tail: neurons 126, 127.
    {
        float4 xv[8];
#pragma unroll
        for (int r = 0; r < 2; r++) {
            const float4* p = xb + (size_t)(126 + r) * nstride;
#pragma unroll
            for (int k = 0; k < 4; k++)
                xv[4 * r + k] = p[lane + 32 * k];
        }
#pragma unroll
        for (int r = 0; r < 2; r++) {
            float pa = 0.0f;
            const float4* w = wq + (size_t)(126 + r) * (N_RULES / 4);
#pragma unroll
            for (int k = 0; k < 4; k++) {
                float4 wv = w[lane + 32 * k];
                pa = fmaf(xv[4 * r + k].x, wv.x, pa);
                pa = fmaf(xv[4 * r + k].y, wv.y, pa);
                pa = fmaf(xv[4 * r + k].z, wv.z, pa);
                pa = fmaf(xv[4 * r + k].w, wv.w, pa);
            }
            acc0 = fmaf(pa, fw0[126 + r], acc0);
            acc1 = fmaf(pa, fw1[126 + r], acc1);
        }
    }

    // Warp reduction of the two logit accumulators.
#pragma unroll
    for (int off = 16; off; off >>= 1) {
        acc0 += __shfl_xor_sync(0xFFFFFFFFu, acc0, off);
        acc1 += __shfl_xor_sync(0xFFFFFFFFu, acc1, off);
    }

    if (lane == 0) {
        float l0 = acc0 + foot_b[0];
        float l1 = acc1 + foot_b[1];
        float m  = fmaxf(l0, l1);
        float e0 = __expf(l0 - m);
        float e1 = __expf(l1 - m);
        float inv = 1.0f / (e0 + e1);
        out[b * 2 + 0] = e0 * inv;
        out[b * 2 + 1] = e1 * inv;
    }
}

extern "C" void kernel_launch(void* const* d_in, const int* in_sizes, int n_in,
                              void* d_out, int out_size)
{
    const float* x      = (const float*)d_in[0];
    const float* head_w = (const float*)d_in[1];
    const float* head_b = (const float*)d_in[2];
    const float* foot_w = (const float*)d_in[3];
    const float* foot_b = (const float*)d_in[4];
    float* out = (float*)d_out;

    // 4096 warps total, one per batch element: 1024 blocks x 128 threads.
    lei_fused_kernel<<<BATCH / 4, 128>>>(x, head_w, head_b, foot_w, foot_b, out);
}

// round 15
// speedup vs baseline: 1.1736x; 1.1736x over previous
#include <cuda_runtime.h>
#include <cuda_bf16.h>

#define N_NEURON 128
#define N_RULES  512
#define BATCH    4096

// FINAL (converged R2 configuration; best measured 153.86us on this exact source).
// One warp per batch element b, fully fused:
//   logit_j[b] = sum_n foot_w[j,n]*( x[n,b,:].head_w[n,:] + head_b[n] ) + foot_b[j]
// then 2-way softmax. Per-lane weighted accumulators; one warp-reduce at the end.
//
// Measured optimum on every axis (all alternatives probed and rejected):
//  - MLP depth: 8 front-batched LDG.128/warp/iter is an interior maximum
//    (~2-deep: 72% DRAM, 4-deep/40w: 80%, 8-deep/27.7w: 85.4%, 12-deep/24w: 72%
//     -- deeper overflows the L1tex wavefront queue, nw*n_LDG*nL >> 248).
//  - __launch_bounds__(128, 8) is LOAD-BEARING: forces the 64-reg budget that
//    keeps the 8-float4 batch live (unbounded -> 40 regs, de-batched, -19%).
//  - Warp count: 2x warps via split-n regressed (-7%); L2 prefetch (-15%); __ldcs (0).
//  - head_w (256 KB) cache-resident: DRAM bytes == sizeof(x) == 1.0737 GB exactly.
// Achieved 6.90 TB/s == B300 path-independent LTS chip cap -> hardware ceiling.
__global__ void __launch_bounds__(128, 8) lei_fused_kernel(
    const float* __restrict__ x,
    const float* __restrict__ head_w,
    const float* __restrict__ head_b,
    const float* __restrict__ foot_w,
    const float* __restrict__ foot_b,
    float* __restrict__ out)
{
    const int warp = threadIdx.x >> 5;
    const int lane = threadIdx.x & 31;
    const int b = blockIdx.x * 4 + warp;   // 1024 blocks * 4 warps = 4096

    const float* __restrict__ fw0 = foot_w;            // [128]
    const float* __restrict__ fw1 = foot_w + N_NEURON; // [128]

    float acc0 = 0.0f, acc1 = 0.0f;

    // Fold the head bias contribution: sum_n head_b[n]*fw_j[n], split across lanes.
#pragma unroll
    for (int k = 0; k < 4; k++) {
        int n = 32 * k + lane;
        float hb = head_b[n];
        acc0 = fmaf(hb, fw0[n], acc0);
        acc1 = fmaf(hb, fw1[n], acc1);
    }

    const float4* __restrict__ xb =
        reinterpret_cast<const float4*>(x) + (size_t)b * (N_RULES / 4);
    const size_t nstride = (size_t)BATCH * (N_RULES / 4);  // float4 stride between neurons
    const float4* __restrict__ wq = reinterpret_cast<const float4*>(head_w);

    for (int n = 0; n < N_NEURON; n += 2) {
        // Front-batch 8 x loads (2 neurons' rows) for MLP.
        const float4* p0 = xb + (size_t)n * nstride;
        const float4* p1 = p0 + nstride;
        float4 xv[8];
#pragma unroll
        for (int k = 0; k < 4; k++) xv[k] = p0[lane + 32 * k];
#pragma unroll
        for (int k = 0; k < 4; k++) xv[4 + k] = p1[lane + 32 * k];

        float pa = 0.0f, pb = 0.0f;
#pragma unroll
        for (int k = 0; k < 4; k++) {
            float4 wv = wq[(size_t)n * (N_RULES / 4) + lane + 32 * k];
            pa = fmaf(xv[k].x, wv.x, pa);
            pa = fmaf(xv[k].y, wv.y, pa);
            pa = fmaf(xv[k].z, wv.z, pa);
            pa = fmaf(xv[k].w, wv.w, pa);
        }
#pragma unroll
        for (int k = 0; k < 4; k++) {
            float4 wv = wq[(size_t)(n + 1) * (N_RULES / 4) + lane + 32 * k];
            pb = fmaf(xv[4 + k].x, wv.x, pb);
            pb = fmaf(xv[4 + k].y, wv.y, pb);
            pb = fmaf(xv[4 + k].z, wv.z, pb);
            pb = fmaf(xv[4 + k].w, wv.w, pb);
        }

        acc0 = fmaf(pa, fw0[n], acc0);
        acc1 = fmaf(pa, fw1[n], acc1);
        acc0 = fmaf(pb, fw0[n + 1], acc0);
        acc1 = fmaf(pb, fw1[n + 1], acc1);
    }

    // Warp reduction of the two logit accumulators.
#pragma unroll
    for (int off = 16; off; off >>= 1) {
        acc0 += __shfl_xor_sync(0xFFFFFFFFu, acc0, off);
        acc1 += __shfl_xor_sync(0xFFFFFFFFu, acc1, off);
    }

    if (lane == 0) {
        float l0 = acc0 + foot_b[0];
        float l1 = acc1 + foot_b[1];
        float m  = fmaxf(l0, l1);
        float e0 = __expf(l0 - m);
        float e1 = __expf(l1 - m);
        float inv = 1.0f / (e0 + e1);
        out[b * 2 + 0] = e0 * inv;
        out[b * 2 + 1] = e1 * inv;
    }
}

extern "C" void kernel_launch(void* const* d_in, const int* in_sizes, int n_in,
                              void* d_out, int out_size)
{
    const float* x      = (const float*)d_in[0];
    const float* head_w = (const float*)d_in[1];
    const float* head_b = (const float*)d_in[2];
    const float* foot_w = (const float*)d_in[3];
    const float* foot_b = (const float*)d_in[4];
    float* out = (float*)d_out;

    // 4096 warps total, one per batch element: 1024 blocks x 128 threads.
    lei_fused_kernel<<<BATCH / 4, 128>>>(x, head_w, head_b, foot_w, foot_b, out);
}

// round 17
// speedup vs baseline: 1.1741x; 1.0004x over previous
#include <cuda_runtime.h>
#include <cuda_bf16.h>

#define N_NEURON 128
#define N_RULES  512
#define BATCH    4096
#define HALF_N   (N_NEURON / 2)

// Page-local variant: each warp covers 2 ADJACENT batch elements (b0, b0+1)
// over one n-half (64 neurons). The 8 front-batched LDG.128 per iteration span
// one contiguous 4 KB region (rows (n,b0) and (n,b0+1) are adjacent in x),
// instead of two rows 8 MB apart. Same warp count (4096) and MLP depth (8)
// as the converged R2 config; only the DRAM page locality changes.
// head_w row is loaded once and reused for both b's.
__global__ void __launch_bounds__(128, 8) lei_fused_kernel(
    const float* __restrict__ x,
    const float* __restrict__ head_w,
    const float* __restrict__ head_b,
    const float* __restrict__ foot_w,
    const float* __restrict__ foot_b,
    float* __restrict__ out)
{
    const int warp = threadIdx.x >> 5;
    const int lane = threadIdx.x & 31;
    const int bl   = warp & 1;    // which b-pair within the CTA (2 pairs/CTA)
    const int half = warp >> 1;   // which neuron half [half*64, half*64+64)
    const int pair = blockIdx.x * 2 + bl;
    const int b0   = pair * 2;    // this warp handles b0 and b0+1

    __shared__ float s[2][2][2];  // [bl][b in pair][logit]

    const float* __restrict__ fw0 = foot_w;            // [128]
    const float* __restrict__ fw1 = foot_w + N_NEURON; // [128]

    // Per-b logit accumulators.
    float a00 = 0.0f, a10 = 0.0f;  // b0: logit0, logit1
    float a01 = 0.0f, a11 = 0.0f;  // b1: logit0, logit1

    // Bias fold over this half's neurons (identical for both b's).
    float bias0 = 0.0f, bias1 = 0.0f;
#pragma unroll
    for (int k = 0; k < 2; k++) {
        int n = half * HALF_N + 32 * k + lane;
        float hb = head_b[n];
        bias0 = fmaf(hb, fw0[n], bias0);
        bias1 = fmaf(hb, fw1[n], bias1);
    }
    a00 += bias0; a10 += bias1;
    a01 += bias0; a11 += bias1;

    const size_t nstride = (size_t)BATCH * (N_RULES / 4);  // float4 stride between neurons
    const float4* __restrict__ xp =
        reinterpret_cast<const float4*>(x)
        + (size_t)(half * HALF_N) * nstride + (size_t)b0 * (N_RULES / 4) + lane;
    const float4* __restrict__ wp =
        reinterpret_cast<const float4*>(head_w)
        + (size_t)(half * HALF_N) * (N_RULES / 4) + lane;

    const int n_begin = half * HALF_N;
    for (int i = 0; i < HALF_N; i++) {
        // 8 front-batched loads spanning 4 KB contiguous: b0's row then b1's row.
        float4 xv[8];
#pragma unroll
        for (int k = 0; k < 4; k++) xv[k]     = xp[32 * k];                 // (n, b0)
#pragma unroll
        for (int k = 0; k < 4; k++) xv[4 + k] = xp[(N_RULES / 4) + 32 * k]; // (n, b0+1)
        xp += nstride;

        float p0 = 0.0f, p1 = 0.0f;
#pragma unroll
        for (int k = 0; k < 4; k++) {
            float4 wv = wp[32 * k];   // one w row, shared by both b's
            p0 = fmaf(xv[k].x, wv.x, p0);
            p0 = fmaf(xv[k].y, wv.y, p0);
            p0 = fmaf(xv[k].z, wv.z, p0);
            p0 = fmaf(xv[k].w, wv.w, p0);
            p1 = fmaf(xv[4 + k].x, wv.x, p1);
            p1 = fmaf(xv[4 + k].y, wv.y, p1);
            p1 = fmaf(xv[4 + k].z, wv.z, p1);
            p1 = fmaf(xv[4 + k].w, wv.w, p1);
        }
        wp += N_RULES / 4;

        const int n = n_begin + i;
        const float w0 = fw0[n], w1 = fw1[n];
        a00 = fmaf(p0, w0, a00);
        a10 = fmaf(p0, w1, a10);
        a01 = fmaf(p1, w0, a01);
        a11 = fmaf(p1, w1, a11);
    }

    // Warp reduction of the four partial accumulators.
#pragma unroll
    for (int off = 16; off; off >>= 1) {
        a00 += __shfl_xor_sync(0xFFFFFFFFu, a00, off);
        a10 += __shfl_xor_sync(0xFFFFFFFFu, a10, off);
        a01 += __shfl_xor_sync(0xFFFFFFFFu, a01, off);
        a11 += __shfl_xor_sync(0xFFFFFFFFu, a11, off);
    }

    // Combine the two n-halves through smem; half 0 finishes both b's.
    if (half == 1 && lane == 0) {
        s[bl][0][0] = a00; s[bl][0][1] = a10;
        s[bl][1][0] = a01; s[bl][1][1] = a11;
    }
    __syncthreads();

    if (half == 0 && lane == 0) {
        // b0
        {
            float l0 = a00 + s[bl][0][0] + foot_b[0];
            float l1 = a10 + s[bl][0][1] + foot_b[1];
            float m = fmaxf(l0, l1);
            float e0 = __expf(l0 - m);
            float e1 = __expf(l1 - m);
            float inv = 1.0f / (e0 + e1);
            out[b0 * 2 + 0] = e0 * inv;
            out[b0 * 2 + 1] = e1 * inv;
        }
        // b0 + 1
        {
            float l0 = a01 + s[bl][1][0] + foot_b[0];
            float l1 = a11 + s[bl][1][1] + foot_b[1];
            float m = fmaxf(l0, l1);
            float e0 = __expf(l0 - m);
            float e1 = __expf(l1 - m);
            float inv = 1.0f / (e0 + e1);
            out[(b0 + 1) * 2 + 0] = e0 * inv;
            out[(b0 + 1) * 2 + 1] = e1 * inv;
        }
    }
}

extern "C" void kernel_launch(void* const* d_in, const int* in_sizes, int n_in,
                              void* d_out, int out_size)
{
    const float* x      = (const float*)d_in[0];
    const float* head_w = (const float*)d_in[1];
    const float* head_b = (const float*)d_in[2];
    const float* foot_w = (const float*)d_in[3];
    const float* foot_b = (const float*)d_in[4];
    float* out = (float*)d_out;

    // 4096 warps total: 1024 blocks x 128 threads
    // (2 b-pairs per CTA x 2 n-halves = 4 warps).
    lei_fused_kernel<<<BATCH / 4, 128>>>(x, head_w, head_b, foot_w, foot_b, out);
}